// round 12
// baseline (speedup 1.0000x reference)
#include <cuda_runtime.h>
#include <cuda_bf16.h>
#include <cstdint>

#define BB   2
#define TT   2048
#define CC   1024
#define HH   16
#define DD   64
#define C3   3072
#define MM   (BB * TT)        // 4096

// ---------------- scratch (static device globals; no allocations) -------------
__device__ __nv_bfloat16 g_xhi[MM * CC];           // x split [M,K]
__device__ __nv_bfloat16 g_xlo[MM * CC];
__device__ __nv_bfloat16 g_wqhi[C3 * CC];          // Wqkv^T split [N,K]
__device__ __nv_bfloat16 g_wqlo[C3 * CC];
__device__ __nv_bfloat16 g_wphi[CC * CC];          // Wproj^T split [N,K]
__device__ __nv_bfloat16 g_wplo[CC * CC];
__device__ __nv_bfloat16 g_yhi[MM * CC];           // attention out split [B,T,C]
__device__ __nv_bfloat16 g_ylo[MM * CC];

// Q/K/V bf16 hi/lo in [B,H,T,D] (Q pre-scaled by 1/8)
__device__ __nv_bfloat16 g_qh[MM * CC];
__device__ __nv_bfloat16 g_ql[MM * CC];
__device__ __nv_bfloat16 g_kh[MM * CC];
__device__ __nv_bfloat16 g_kl[MM * CC];
__device__ __nv_bfloat16 g_vh[MM * CC];
__device__ __nv_bfloat16 g_vl[MM * CC];

// ---------------- helpers ------------------------------------------------------
__device__ __forceinline__ uint32_t smem_u32(const void* p) {
    uint32_t a;
    asm("{ .reg .u64 t; cvta.to.shared.u64 t, %1; cvt.u32.u64 %0, t; }"
        : "=r"(a) : "l"(p));
    return a;
}

__device__ __forceinline__ void ldsm_x4(uint32_t r[4], uint32_t addr) {
    asm volatile("ldmatrix.sync.aligned.m8n8.x4.shared.b16 {%0,%1,%2,%3}, [%4];"
                 : "=r"(r[0]), "=r"(r[1]), "=r"(r[2]), "=r"(r[3]) : "r"(addr));
}

__device__ __forceinline__ void ldsm_x4_t(uint32_t r[4], uint32_t addr) {
    asm volatile("ldmatrix.sync.aligned.m8n8.x4.trans.shared.b16 {%0,%1,%2,%3}, [%4];"
                 : "=r"(r[0]), "=r"(r[1]), "=r"(r[2]), "=r"(r[3]) : "r"(addr));
}

__device__ __forceinline__ void mma_bf16(float d[4], const uint32_t a[4],
                                         const uint32_t b[2]) {
    asm volatile(
        "mma.sync.aligned.m16n8k16.row.col.f32.bf16.bf16.f32 "
        "{%0,%1,%2,%3}, {%4,%5,%6,%7}, {%8,%9}, {%0,%1,%2,%3};"
        : "+f"(d[0]), "+f"(d[1]), "+f"(d[2]), "+f"(d[3])
        : "r"(a[0]), "r"(a[1]), "r"(a[2]), "r"(a[3]), "r"(b[0]), "r"(b[1]));
}

// split two floats into packed bf16x2 hi + lo(residual)
__device__ __forceinline__ void split2(float a, float b, uint32_t& hi, uint32_t& lo) {
    __nv_bfloat162 h = __floats2bfloat162_rn(a, b);
    hi = *(uint32_t*)&h;
    float ra = a - __bfloat162float(h.x);
    float rb = b - __bfloat162float(h.y);
    __nv_bfloat162 l2 = __floats2bfloat162_rn(ra, rb);
    lo = *(uint32_t*)&l2;
}

// ---------------- pre-pass: fp32 -> bf16 hi/lo split --------------------------
__global__ void split_kernel(const float* __restrict__ A,
                             __nv_bfloat16* __restrict__ hi,
                             __nv_bfloat16* __restrict__ lo, int n)
{
    int i = blockIdx.x * 256 + threadIdx.x;
    if (i < n) {
        float v = A[i];
        __nv_bfloat16 h = __float2bfloat16(v);
        hi[i] = h;
        lo[i] = __float2bfloat16(v - __bfloat162float(h));
    }
}

// transpose + split: W [K,N] fp32 -> hi/lo [N,K] bf16
__global__ void tsplit_kernel(const float* __restrict__ W,
                              __nv_bfloat16* __restrict__ hi,
                              __nv_bfloat16* __restrict__ lo, int K, int N)
{
    __shared__ float t[32][33];
    int k0 = blockIdx.y * 32, n0 = blockIdx.x * 32;
    int tx = threadIdx.x, ty = threadIdx.y;   // block (32,8)
#pragma unroll
    for (int i = 0; i < 32; i += 8)
        t[ty + i][tx] = W[(size_t)(k0 + ty + i) * N + n0 + tx];
    __syncthreads();
#pragma unroll
    for (int i = 0; i < 32; i += 8) {
        float v = t[tx][ty + i];
        size_t o = (size_t)(n0 + ty + i) * K + k0 + tx;
        __nv_bfloat16 h = __float2bfloat16(v);
        hi[o] = h;
        lo[o] = __float2bfloat16(v - __bfloat162float(h));
    }
}

// ---------------- mma.sync bf16 split GEMM (double-buffered) ------------------
// C[M,N] = A[M,K] @ Bt[N,K]^T + bias, fp32 accum.
// CTA tile 128x128, BK=32, 8 warps (4m x 2n), warp tile 32x64.
// Two smem stages, ONE barrier per chunk: loads for chunk c+1 (plain LDG->STS
// into the other stage) are issued before the MMA phase of chunk c.
#define GBM 128
#define GBN 128
#define GBK 32
#define KPAD 40                          // bf16 elems per row (80 B)
#define OFF_AH 0
#define OFF_AL 10240
#define OFF_BH 20480
#define OFF_BL 30720
#define GSTG  40960                      // one stage
#define GSMEM (2 * GSTG)                 // 81920 B

__device__ __forceinline__ void gemm_load_chunk(
    unsigned char* smem, int stoff,
    const __nv_bfloat16* __restrict__ Ahi, const __nv_bfloat16* __restrict__ Alo,
    const __nv_bfloat16* __restrict__ Bhi, const __nv_bfloat16* __restrict__ Blo,
    int m0, int n0, int k0, int K, int tid)
{
#pragma unroll
    for (int it = 0; it < 2; it++) {
        int row = (tid >> 2) + it * 64;
        int c8  = (tid & 3) * 8;
        int s   = stoff + (row * KPAD + c8) * 2;
        size_t ga = (size_t)(m0 + row) * K + k0 + c8;
        size_t gb = (size_t)(n0 + row) * K + k0 + c8;
        *(uint4*)(smem + s + OFF_AH) = *(const uint4*)(Ahi + ga);
        *(uint4*)(smem + s + OFF_AL) = *(const uint4*)(Alo + ga);
        *(uint4*)(smem + s + OFF_BH) = *(const uint4*)(Bhi + gb);
        *(uint4*)(smem + s + OFF_BL) = *(const uint4*)(Blo + gb);
    }
}

template <int EPIROPE>
__global__ void __launch_bounds__(256, 2)
gemm_mma_kernel(const __nv_bfloat16* __restrict__ Ahi,
                const __nv_bfloat16* __restrict__ Alo,
                const __nv_bfloat16* __restrict__ Bhi,
                const __nv_bfloat16* __restrict__ Blo,
                const float* __restrict__ bias,
                const float* __restrict__ cosT,
                const float* __restrict__ sinT,
                float* __restrict__ Cm,
                int N, int K)
{
    extern __shared__ __align__(16) unsigned char smem[];
    const uint32_t sb = smem_u32(smem);

    const int tid  = threadIdx.x;
    const int lane = tid & 31;
    const int w    = tid >> 5;
    const int m_base = (w & 3) * 32;    // warp m offset
    const int n_base = (w >> 2) * 64;   // warp n offset

    const int m0 = blockIdx.y * GBM;
    const int n0 = blockIdx.x * GBN;

    float d[2][8][4];
#pragma unroll
    for (int i = 0; i < 2; i++)
#pragma unroll
        for (int j = 0; j < 8; j++)
#pragma unroll
            for (int r = 0; r < 4; r++) d[i][j][r] = 0.f;

    const int a_m   = m_base + (lane & 7) + ((lane >> 3) & 1) * 8;
    const int a_khi = (lane >> 4) * 8;
    const int b_g   = lane >> 3;
    const int b_n8  = (b_g >> 1) * 8 + (lane & 7);
    const int b_k8  = (b_g & 1) * 8;

    const int NC = K / GBK;
    gemm_load_chunk(smem, 0, Ahi, Alo, Bhi, Blo, m0, n0, 0, K, tid);
    __syncthreads();

    for (int c = 0; c < NC; c++) {
        if (c + 1 < NC)
            gemm_load_chunk(smem, ((c + 1) & 1) * GSTG, Ahi, Alo, Bhi, Blo,
                            m0, n0, (c + 1) * GBK, K, tid);

        const uint32_t st = sb + (c & 1) * GSTG;
#pragma unroll
        for (int ks = 0; ks < 2; ks++) {
            const int koff = ks * 16;
            uint32_t ah[2][4], al[2][4];
#pragma unroll
            for (int mf = 0; mf < 2; mf++) {
                uint32_t off = (uint32_t)((a_m + mf * 16) * KPAD + koff + a_khi) * 2;
                ldsm_x4(ah[mf], st + OFF_AH + off);
                ldsm_x4(al[mf], st + OFF_AL + off);
            }
#pragma unroll
            for (int pr = 0; pr < 4; pr++) {
                uint32_t off = (uint32_t)((n_base + pr * 16 + b_n8) * KPAD + koff + b_k8) * 2;
                uint32_t rh[4], rl[4];
                ldsm_x4(rh, st + OFF_BH + off);
                ldsm_x4(rl, st + OFF_BL + off);
                uint32_t bh0[2] = {rh[0], rh[1]}, bh1[2] = {rh[2], rh[3]};
                uint32_t bl0[2] = {rl[0], rl[1]}, bl1[2] = {rl[2], rl[3]};
#pragma unroll
                for (int mf = 0; mf < 2; mf++) {
                    mma_bf16(d[mf][pr * 2 + 0], ah[mf], bh0);
                    mma_bf16(d[mf][pr * 2 + 0], ah[mf], bl0);
                    mma_bf16(d[mf][pr * 2 + 0], al[mf], bh0);
                    mma_bf16(d[mf][pr * 2 + 1], ah[mf], bh1);
                    mma_bf16(d[mf][pr * 2 + 1], ah[mf], bl1);
                    mma_bf16(d[mf][pr * 2 + 1], al[mf], bh1);
                }
            }
        }
        __syncthreads();
    }

    if (EPIROPE) {
        // 128-col tiles never straddle a q/k/v boundary (1024 % 128 == 0)
        const int sec = n0 >> 10;            // 0=q 1=k 2=v
#pragma unroll
        for (int mf = 0; mf < 2; mf++) {
            int row = m0 + m_base + mf * 16 + (lane >> 2);
#pragma unroll
            for (int rr = 0; rr < 2; rr++) {
                int r = row + rr * 8;
                int t = r & (TT - 1), b = r >> 11;
#pragma unroll
                for (int nf = 0; nf < 8; nf++) {
                    int ncol = n0 + n_base + nf * 8 + 2 * (lane & 3);  // even
                    int h    = (ncol & 1023) >> 6;
                    int dcol = ncol & 63;
                    size_t obase = ((size_t)(b * HH + h) * TT + t) * DD + dcol;
                    float v0 = d[mf][nf][rr * 2 + 0] + bias[ncol];
                    float v1 = d[mf][nf][rr * 2 + 1] + bias[ncol + 1];
                    uint32_t hi, lo;
                    if (sec == 2) {
                        split2(v0, v1, hi, lo);
                        *(uint32_t*)&g_vh[obase] = hi;
                        *(uint32_t*)&g_vl[obase] = lo;
                    } else {
                        int i = dcol >> 1;
                        float c = cosT[t * 32 + i], s = sinT[t * 32 + i];
                        float r0 = v0 * c - v1 * s;
                        float r1 = v0 * s + v1 * c;
                        if (sec == 0) {
                            split2(r0 * 0.125f, r1 * 0.125f, hi, lo);
                            *(uint32_t*)&g_qh[obase] = hi;
                            *(uint32_t*)&g_ql[obase] = lo;
                        } else {
                            split2(r0, r1, hi, lo);
                            *(uint32_t*)&g_kh[obase] = hi;
                            *(uint32_t*)&g_kl[obase] = lo;
                        }
                    }
                }
            }
        }
    } else {
#pragma unroll
        for (int mf = 0; mf < 2; mf++) {
#pragma unroll
            for (int nf = 0; nf < 8; nf++) {
                int row = m0 + m_base + mf * 16 + (lane >> 2);
                int col = n0 + n_base + nf * 8 + 2 * (lane & 3);
                float bx = bias[col], by = bias[col + 1];
                float2 v0 = {d[mf][nf][0] + bx, d[mf][nf][1] + by};
                float2 v1 = {d[mf][nf][2] + bx, d[mf][nf][3] + by};
                *(float2*)&Cm[(size_t)row * N + col]       = v0;
                *(float2*)&Cm[(size_t)(row + 8) * N + col] = v1;
            }
        }
    }
}

// ---------------- tensor-core causal flash attention (double-buffered) --------
// BQ=128, BKV=64, 8 warps x 16 q-rows. Q frags register-resident.
// Two KV smem stages, ONE barrier per chunk; loads for chunk ch+1 issued
// before the MMA/softmax phase of chunk ch.
#define FKP 72
#define F_KH 0
#define F_KL 9216
#define F_VH 18432
#define F_VL 27648
#define FS   36864                       // one stage
#define F_QH 0                           // Q staged in stage 0 before mainloop
#define F_QL 18432
#define FLASH_SMEM (2 * FS)              // 73728 B

__device__ __forceinline__ void flash_load_chunk(
    unsigned char* smem, int stoff,
    const __nv_bfloat16* __restrict__ Kh, const __nv_bfloat16* __restrict__ Kl,
    const __nv_bfloat16* __restrict__ Vh, const __nv_bfloat16* __restrict__ Vl,
    size_t gbase, int kv0, int tid)
{
#pragma unroll
    for (int it = 0; it < 2; it++) {
        int u = tid + it * 256;              // 0..511
        int row = u >> 3, c8 = (u & 7) * 8;
        size_t g = gbase + (size_t)(kv0 + row) * DD + c8;
        int s = stoff + (row * FKP + c8) * 2;
        *(uint4*)(smem + s + F_KH) = *(const uint4*)(Kh + g);
        *(uint4*)(smem + s + F_KL) = *(const uint4*)(Kl + g);
        *(uint4*)(smem + s + F_VH) = *(const uint4*)(Vh + g);
        *(uint4*)(smem + s + F_VL) = *(const uint4*)(Vl + g);
    }
}

__global__ void __launch_bounds__(256, 2)
flash_mma_kernel(const __nv_bfloat16* __restrict__ Qh,
                 const __nv_bfloat16* __restrict__ Ql,
                 const __nv_bfloat16* __restrict__ Kh,
                 const __nv_bfloat16* __restrict__ Kl,
                 const __nv_bfloat16* __restrict__ Vh,
                 const __nv_bfloat16* __restrict__ Vl)
{
    extern __shared__ __align__(16) unsigned char smem[];
    const uint32_t sb = smem_u32(smem);
    const int tid  = threadIdx.x;
    const int lane = tid & 31;
    const int w    = tid >> 5;

    const int qt = gridDim.x - 1 - blockIdx.x;   // heavy tiles first
    const int q0 = qt * 128;
    const int bh = blockIdx.y;
    const size_t gbase = (size_t)bh * TT * DD;

    // ---- stage Q tile (hi/lo) into stage-0 smem ----
#pragma unroll
    for (int it = 0; it < 4; it++) {
        int u = tid + it * 256;                  // 0..1023
        int row = u >> 3, c8 = (u & 7) * 8;
        size_t g = gbase + (size_t)(q0 + row) * DD + c8;
        int s = row * FKP + c8;
        *(uint4*)(smem + F_QH + s * 2) = *(const uint4*)(Qh + g);
        *(uint4*)(smem + F_QL + s * 2) = *(const uint4*)(Ql + g);
    }
    __syncthreads();

    // ---- Q fragments into registers ----
    const int a_m   = w * 16 + (lane & 7) + ((lane >> 3) & 1) * 8;
    const int a_khi = (lane >> 4) * 8;
    uint32_t qh[4][4], ql[4][4];
#pragma unroll
    for (int ks = 0; ks < 4; ks++) {
        uint32_t off = (uint32_t)(a_m * FKP + ks * 16 + a_khi) * 2;
        ldsm_x4(qh[ks], sb + F_QH + off);
        ldsm_x4(ql[ks], sb + F_QL + off);
    }
    __syncthreads();   // Q smem free; stage 0 becomes KV buffer

    const int b_g   = lane >> 3;
    const int b_n8  = (b_g >> 1) * 8 + (lane & 7);
    const int b_k8  = (b_g & 1) * 8;
    const int v_r8  = (b_g & 1) * 8 + (lane & 7);
    const int v_c8  = (b_g >> 1) * 8;

    float o[8][4];
#pragma unroll
    for (int nf = 0; nf < 8; nf++)
#pragma unroll
        for (int j = 0; j < 4; j++) o[nf][j] = 0.f;
    float m0 = -1e30f, m1 = -1e30f, l0 = 0.f, l1 = 0.f;

    const int r0g = q0 + w * 16 + (lane >> 2);
    const int nchunk = 2 * qt + 2;

    flash_load_chunk(smem, 0, Kh, Kl, Vh, Vl, gbase, 0, tid);
    __syncthreads();

    for (int ch = 0; ch < nchunk; ch++) {
        const int kv0 = ch * 64;
        if (ch + 1 < nchunk)
            flash_load_chunk(smem, ((ch + 1) & 1) * FS, Kh, Kl, Vh, Vl,
                             gbase, (ch + 1) * 64, tid);

        const uint32_t st = sb + (ch & 1) * FS;

        // ---- S = Q K^T (3-term split) ----
        float s4[8][4];
#pragma unroll
        for (int nf = 0; nf < 8; nf++)
#pragma unroll
            for (int j = 0; j < 4; j++) s4[nf][j] = 0.f;

#pragma unroll
        for (int ks = 0; ks < 4; ks++) {
#pragma unroll
            for (int pr = 0; pr < 4; pr++) {
                uint32_t off = (uint32_t)((pr * 16 + b_n8) * FKP + ks * 16 + b_k8) * 2;
                uint32_t kh4[4], kl4[4];
                ldsm_x4(kh4, st + F_KH + off);
                ldsm_x4(kl4, st + F_KL + off);
                uint32_t bh0[2] = {kh4[0], kh4[1]}, bh1[2] = {kh4[2], kh4[3]};
                uint32_t bl0[2] = {kl4[0], kl4[1]}, bl1[2] = {kl4[2], kl4[3]};
                mma_bf16(s4[2 * pr], qh[ks], bh0);
                mma_bf16(s4[2 * pr], qh[ks], bl0);
                mma_bf16(s4[2 * pr], ql[ks], bh0);
                mma_bf16(s4[2 * pr + 1], qh[ks], bh1);
                mma_bf16(s4[2 * pr + 1], qh[ks], bl1);
                mma_bf16(s4[2 * pr + 1], ql[ks], bh1);
            }
        }

        // ---- causal mask (only last two chunks of this tile) ----
        if (ch >= 2 * qt) {
#pragma unroll
            for (int nf = 0; nf < 8; nf++) {
                int cbase = kv0 + nf * 8 + (lane & 3) * 2;
#pragma unroll
                for (int j = 0; j < 4; j++) {
                    int col = cbase + (j & 1);
                    int row = r0g + ((j >> 1) << 3);
                    if (col > row) s4[nf][j] = -1e30f;
                }
            }
        }

        // ---- online softmax ----
        float mx0 = -1e30f, mx1 = -1e30f;
#pragma unroll
        for (int nf = 0; nf < 8; nf++) {
            mx0 = fmaxf(mx0, fmaxf(s4[nf][0], s4[nf][1]));
            mx1 = fmaxf(mx1, fmaxf(s4[nf][2], s4[nf][3]));
        }
        mx0 = fmaxf(mx0, __shfl_xor_sync(0xffffffffu, mx0, 1));
        mx0 = fmaxf(mx0, __shfl_xor_sync(0xffffffffu, mx0, 2));
        mx1 = fmaxf(mx1, __shfl_xor_sync(0xffffffffu, mx1, 1));
        mx1 = fmaxf(mx1, __shfl_xor_sync(0xffffffffu, mx1, 2));
        float mn0 = fmaxf(m0, mx0), mn1 = fmaxf(m1, mx1);
        float al0 = __expf(m0 - mn0), al1 = __expf(m1 - mn1);
        float sum0 = 0.f, sum1 = 0.f;
#pragma unroll
        for (int nf = 0; nf < 8; nf++) {
            s4[nf][0] = __expf(s4[nf][0] - mn0);
            s4[nf][1] = __expf(s4[nf][1] - mn0);
            s4[nf][2] = __expf(s4[nf][2] - mn1);
            s4[nf][3] = __expf(s4[nf][3] - mn1);
            sum0 += s4[nf][0] + s4[nf][1];
            sum1 += s4[nf][2] + s4[nf][3];
        }
        sum0 += __shfl_xor_sync(0xffffffffu, sum0, 1);
        sum0 += __shfl_xor_sync(0xffffffffu, sum0, 2);
        sum1 += __shfl_xor_sync(0xffffffffu, sum1, 1);
        sum1 += __shfl_xor_sync(0xffffffffu, sum1, 2);
        l0 = l0 * al0 + sum0;  m0 = mn0;
        l1 = l1 * al1 + sum1;  m1 = mn1;
#pragma unroll
        for (int nf = 0; nf < 8; nf++) {
            o[nf][0] *= al0; o[nf][1] *= al0;
            o[nf][2] *= al1; o[nf][3] *= al1;
        }

        // ---- O += P V (3-term split, P from registers) ----
#pragma unroll
        for (int ks = 0; ks < 4; ks++) {
            uint32_t pa_h[4], pa_l[4];
            split2(s4[2 * ks][0],     s4[2 * ks][1],     pa_h[0], pa_l[0]);
            split2(s4[2 * ks][2],     s4[2 * ks][3],     pa_h[1], pa_l[1]);
            split2(s4[2 * ks + 1][0], s4[2 * ks + 1][1], pa_h[2], pa_l[2]);
            split2(s4[2 * ks + 1][2], s4[2 * ks + 1][3], pa_h[3], pa_l[3]);
#pragma unroll
            for (int pr = 0; pr < 4; pr++) {
                uint32_t off = (uint32_t)((ks * 16 + v_r8) * FKP + pr * 16 + v_c8) * 2;
                uint32_t vh4[4], vl4[4];
                ldsm_x4_t(vh4, st + F_VH + off);
                ldsm_x4_t(vl4, st + F_VL + off);
                uint32_t bh0[2] = {vh4[0], vh4[1]}, bh1[2] = {vh4[2], vh4[3]};
                uint32_t bl0[2] = {vl4[0], vl4[1]}, bl1[2] = {vl4[2], vl4[3]};
                mma_bf16(o[2 * pr], pa_h, bh0);
                mma_bf16(o[2 * pr], pa_h, bl0);
                mma_bf16(o[2 * pr], pa_l, bh0);
                mma_bf16(o[2 * pr + 1], pa_h, bh1);
                mma_bf16(o[2 * pr + 1], pa_h, bl1);
                mma_bf16(o[2 * pr + 1], pa_l, bh1);
            }
        }
        __syncthreads();
    }

    // ---- epilogue: O /= l, write bf16 hi/lo to [B,T,C] ----
    float inv0 = 1.f / l0, inv1 = 1.f / l1;
    int b = bh >> 4, h = bh & 15;
    size_t base0 = ((size_t)(b * TT + r0g)) * CC + h * DD;
    size_t base1 = ((size_t)(b * TT + r0g + 8)) * CC + h * DD;
#pragma unroll
    for (int nf = 0; nf < 8; nf++) {
        int c = nf * 8 + (lane & 3) * 2;
        uint32_t hi, lo;
        split2(o[nf][0] * inv0, o[nf][1] * inv0, hi, lo);
        *(uint32_t*)&g_yhi[base0 + c] = hi;
        *(uint32_t*)&g_ylo[base0 + c] = lo;
        split2(o[nf][2] * inv1, o[nf][3] * inv1, hi, lo);
        *(uint32_t*)&g_yhi[base1 + c] = hi;
        *(uint32_t*)&g_ylo[base1 + c] = lo;
    }
}

// ---------------- launcher ----------------------------------------------------
extern "C" void kernel_launch(void* const* d_in, const int* in_sizes, int n_in,
                              void* d_out, int out_size)
{
    const float* x     = (const float*)d_in[0];
    const float* Wqkv  = (const float*)d_in[1];
    const float* bqkv  = (const float*)d_in[2];
    const float* Wproj = (const float*)d_in[3];
    const float* bproj = (const float*)d_in[4];
    const float* cosT  = (const float*)d_in[5];
    const float* sinT  = (const float*)d_in[6];
    float* out = (float*)d_out;

    __nv_bfloat16 *xhi, *xlo, *wqhi, *wqlo, *wphi, *wplo, *yhi, *ylo;
    __nv_bfloat16 *qh, *ql, *kh, *kl, *vh, *vl;
    cudaGetSymbolAddress((void**)&xhi,  g_xhi);
    cudaGetSymbolAddress((void**)&xlo,  g_xlo);
    cudaGetSymbolAddress((void**)&wqhi, g_wqhi);
    cudaGetSymbolAddress((void**)&wqlo, g_wqlo);
    cudaGetSymbolAddress((void**)&wphi, g_wphi);
    cudaGetSymbolAddress((void**)&wplo, g_wplo);
    cudaGetSymbolAddress((void**)&yhi,  g_yhi);
    cudaGetSymbolAddress((void**)&ylo,  g_ylo);
    cudaGetSymbolAddress((void**)&qh,   g_qh);
    cudaGetSymbolAddress((void**)&ql,   g_ql);
    cudaGetSymbolAddress((void**)&kh,   g_kh);
    cudaGetSymbolAddress((void**)&kl,   g_kl);
    cudaGetSymbolAddress((void**)&vh,   g_vh);
    cudaGetSymbolAddress((void**)&vl,   g_vl);

    static bool attr_set = false;
    if (!attr_set) {
        cudaFuncSetAttribute(gemm_mma_kernel<1>,
                             cudaFuncAttributeMaxDynamicSharedMemorySize, GSMEM);
        cudaFuncSetAttribute(gemm_mma_kernel<0>,
                             cudaFuncAttributeMaxDynamicSharedMemorySize, GSMEM);
        cudaFuncSetAttribute(flash_mma_kernel,
                             cudaFuncAttributeMaxDynamicSharedMemorySize, FLASH_SMEM);
        attr_set = true;
    }

    // pre-pass: split x; transpose+split weights
    split_kernel<<<(MM * CC + 255) / 256, 256>>>(x, xhi, xlo, MM * CC);
    tsplit_kernel<<<dim3(C3 / 32, CC / 32), dim3(32, 8)>>>(Wqkv, wqhi, wqlo, CC, C3);
    tsplit_kernel<<<dim3(CC / 32, CC / 32), dim3(32, 8)>>>(Wproj, wphi, wplo, CC, CC);

    // 1) QKV projection, fused bias+RoPE+split epilogue -> g_qh..g_vl
    gemm_mma_kernel<1><<<dim3(C3 / GBN, MM / GBM), 256, GSMEM>>>(
        xhi, xlo, wqhi, wqlo, bqkv, cosT, sinT, nullptr, C3, CC);

    // 2) tensor-core causal flash attention (writes yhi/ylo in [B,T,C])
    flash_mma_kernel<<<dim3(TT / 128, BB * HH), 256, FLASH_SMEM>>>(
        qh, ql, kh, kl, vh, vl);

    // 3) output projection
    gemm_mma_kernel<0><<<dim3(CC / GBN, MM / GBM), 256, GSMEM>>>(
        yhi, ylo, wphi, wplo, bproj, nullptr, nullptr, out, CC, CC);
}

// round 14
// speedup vs baseline: 1.0928x; 1.0928x over previous
#include <cuda_runtime.h>
#include <cuda_bf16.h>
#include <cstdint>

#define BB   2
#define TT   2048
#define CC   1024
#define HH   16
#define DD   64
#define C3   3072
#define MM   (BB * TT)        // 4096

// ---------------- scratch (static device globals; no allocations) -------------
__device__ __nv_bfloat16 g_xhi[MM * CC];           // x split [M,K]
__device__ __nv_bfloat16 g_xlo[MM * CC];
__device__ __nv_bfloat16 g_wqhi[C3 * CC];          // Wqkv^T split [N,K]
__device__ __nv_bfloat16 g_wqlo[C3 * CC];
__device__ __nv_bfloat16 g_wphi[CC * CC];          // Wproj^T split [N,K]
__device__ __nv_bfloat16 g_wplo[CC * CC];
__device__ __nv_bfloat16 g_yhi[MM * CC];           // attention out split [B,T,C]
__device__ __nv_bfloat16 g_ylo[MM * CC];

// Q/K/V bf16 hi/lo in [B,H,T,D] (Q pre-scaled by 1/8)
__device__ __nv_bfloat16 g_qh[MM * CC];
__device__ __nv_bfloat16 g_ql[MM * CC];
__device__ __nv_bfloat16 g_kh[MM * CC];
__device__ __nv_bfloat16 g_kl[MM * CC];
__device__ __nv_bfloat16 g_vh[MM * CC];
__device__ __nv_bfloat16 g_vl[MM * CC];

// ---------------- helpers ------------------------------------------------------
__device__ __forceinline__ uint32_t smem_u32(const void* p) {
    uint32_t a;
    asm("{ .reg .u64 t; cvta.to.shared.u64 t, %1; cvt.u32.u64 %0, t; }"
        : "=r"(a) : "l"(p));
    return a;
}

__device__ __forceinline__ void ldsm_x4(uint32_t r[4], uint32_t addr) {
    asm volatile("ldmatrix.sync.aligned.m8n8.x4.shared.b16 {%0,%1,%2,%3}, [%4];"
                 : "=r"(r[0]), "=r"(r[1]), "=r"(r[2]), "=r"(r[3]) : "r"(addr));
}

__device__ __forceinline__ void ldsm_x4_t(uint32_t r[4], uint32_t addr) {
    asm volatile("ldmatrix.sync.aligned.m8n8.x4.trans.shared.b16 {%0,%1,%2,%3}, [%4];"
                 : "=r"(r[0]), "=r"(r[1]), "=r"(r[2]), "=r"(r[3]) : "r"(addr));
}

__device__ __forceinline__ void mma_bf16(float d[4], const uint32_t a[4],
                                         const uint32_t b[2]) {
    asm volatile(
        "mma.sync.aligned.m16n8k16.row.col.f32.bf16.bf16.f32 "
        "{%0,%1,%2,%3}, {%4,%5,%6,%7}, {%8,%9}, {%0,%1,%2,%3};"
        : "+f"(d[0]), "+f"(d[1]), "+f"(d[2]), "+f"(d[3])
        : "r"(a[0]), "r"(a[1]), "r"(a[2]), "r"(a[3]), "r"(b[0]), "r"(b[1]));
}

// split two floats into packed bf16x2 hi + lo(residual)
__device__ __forceinline__ void split2(float a, float b, uint32_t& hi, uint32_t& lo) {
    __nv_bfloat162 h = __floats2bfloat162_rn(a, b);
    hi = *(uint32_t*)&h;
    float ra = a - __bfloat162float(h.x);
    float rb = b - __bfloat162float(h.y);
    __nv_bfloat162 l2 = __floats2bfloat162_rn(ra, rb);
    lo = *(uint32_t*)&l2;
}

// ---------------- pre-pass: fp32 -> bf16 hi/lo split --------------------------
__global__ void split_kernel(const float* __restrict__ A,
                             __nv_bfloat16* __restrict__ hi,
                             __nv_bfloat16* __restrict__ lo, int n)
{
    int i = blockIdx.x * 256 + threadIdx.x;
    if (i < n) {
        float v = A[i];
        __nv_bfloat16 h = __float2bfloat16(v);
        hi[i] = h;
        lo[i] = __float2bfloat16(v - __bfloat162float(h));
    }
}

// transpose + split: W [K,N] fp32 -> hi/lo [N,K] bf16
__global__ void tsplit_kernel(const float* __restrict__ W,
                              __nv_bfloat16* __restrict__ hi,
                              __nv_bfloat16* __restrict__ lo, int K, int N)
{
    __shared__ float t[32][33];
    int k0 = blockIdx.y * 32, n0 = blockIdx.x * 32;
    int tx = threadIdx.x, ty = threadIdx.y;   // block (32,8)
#pragma unroll
    for (int i = 0; i < 32; i += 8)
        t[ty + i][tx] = W[(size_t)(k0 + ty + i) * N + n0 + tx];
    __syncthreads();
#pragma unroll
    for (int i = 0; i < 32; i += 8) {
        float v = t[tx][ty + i];
        size_t o = (size_t)(n0 + ty + i) * K + k0 + tx;
        __nv_bfloat16 h = __float2bfloat16(v);
        hi[o] = h;
        lo[o] = __float2bfloat16(v - __bfloat162float(h));
    }
}

// ---------------- mma.sync bf16 split GEMM ------------------------------------
// C[M,N] = A[M,K] @ Bt[N,K]^T + bias, fp32 accum.
// CTA tile 128x128, BK=64, 8 warps (4m x 2n), warp tile 32x64.
// Single smem buffer, max MMAs per barrier (R10 structure — both explicit
// pipelining variants regressed; 2 CTA/SM interleave is the overlap mechanism).
#define GBM 128
#define GBN 128
#define GBK 64
#define KPAD 72
#define OFF_AH 0
#define OFF_AL (128 * KPAD * 2)          // 18432
#define OFF_BH (2 * 128 * KPAD * 2)      // 36864
#define OFF_BL (3 * 128 * KPAD * 2)      // 55296
#define GSMEM  (4 * 128 * KPAD * 2)      // 73728 B

template <int EPIROPE>
__global__ void __launch_bounds__(256, 2)
gemm_mma_kernel(const __nv_bfloat16* __restrict__ Ahi,
                const __nv_bfloat16* __restrict__ Alo,
                const __nv_bfloat16* __restrict__ Bhi,
                const __nv_bfloat16* __restrict__ Blo,
                const float* __restrict__ bias,
                const float* __restrict__ cosT,
                const float* __restrict__ sinT,
                float* __restrict__ Cm,
                int N, int K)
{
    extern __shared__ __align__(16) unsigned char smem[];
    __nv_bfloat16* sAh = (__nv_bfloat16*)(smem + OFF_AH);
    __nv_bfloat16* sAl = (__nv_bfloat16*)(smem + OFF_AL);
    __nv_bfloat16* sBh = (__nv_bfloat16*)(smem + OFF_BH);
    __nv_bfloat16* sBl = (__nv_bfloat16*)(smem + OFF_BL);
    const uint32_t sb = smem_u32(smem);

    const int tid  = threadIdx.x;
    const int lane = tid & 31;
    const int w    = tid >> 5;
    const int m_base = (w & 3) * 32;    // warp m offset
    const int n_base = (w >> 2) * 64;   // warp n offset

    const int m0 = blockIdx.y * GBM;
    const int n0 = blockIdx.x * GBN;

    float d[2][8][4];
#pragma unroll
    for (int i = 0; i < 2; i++)
#pragma unroll
        for (int j = 0; j < 8; j++)
#pragma unroll
            for (int r = 0; r < 4; r++) d[i][j][r] = 0.f;

    const int a_m   = m_base + (lane & 7) + ((lane >> 3) & 1) * 8;
    const int a_khi = (lane >> 4) * 8;
    const int b_g   = lane >> 3;
    const int b_n8  = (b_g >> 1) * 8 + (lane & 7);
    const int b_k8  = (b_g & 1) * 8;

    for (int k0 = 0; k0 < K; k0 += GBK) {
        // ---- load chunk: A and B 128x64 hi/lo tiles (144B padded rows) ----
#pragma unroll
        for (int it = 0; it < 4; it++) {
            int u = tid + it * 256;          // 0..1023
            int row = u >> 3, c8 = (u & 7) * 8;
            int s = row * KPAD + c8;
            size_t ga = (size_t)(m0 + row) * K + k0 + c8;
            size_t gb = (size_t)(n0 + row) * K + k0 + c8;
            *(uint4*)(sAh + s) = *(const uint4*)(Ahi + ga);
            *(uint4*)(sAl + s) = *(const uint4*)(Alo + ga);
            *(uint4*)(sBh + s) = *(const uint4*)(Bhi + gb);
            *(uint4*)(sBl + s) = *(const uint4*)(Blo + gb);
        }
        __syncthreads();

#pragma unroll
        for (int ks = 0; ks < 4; ks++) {
            const int koff = ks * 16;
            uint32_t ah[2][4], al[2][4];
#pragma unroll
            for (int mf = 0; mf < 2; mf++) {
                uint32_t off = (uint32_t)((a_m + mf * 16) * KPAD + koff + a_khi) * 2;
                ldsm_x4(ah[mf], sb + OFF_AH + off);
                ldsm_x4(al[mf], sb + OFF_AL + off);
            }
#pragma unroll
            for (int pr = 0; pr < 4; pr++) {
                uint32_t off = (uint32_t)((n_base + pr * 16 + b_n8) * KPAD + koff + b_k8) * 2;
                uint32_t rh[4], rl[4];
                ldsm_x4(rh, sb + OFF_BH + off);
                ldsm_x4(rl, sb + OFF_BL + off);
                uint32_t bh0[2] = {rh[0], rh[1]}, bh1[2] = {rh[2], rh[3]};
                uint32_t bl0[2] = {rl[0], rl[1]}, bl1[2] = {rl[2], rl[3]};
#pragma unroll
                for (int mf = 0; mf < 2; mf++) {
                    mma_bf16(d[mf][pr * 2 + 0], ah[mf], bh0);
                    mma_bf16(d[mf][pr * 2 + 0], ah[mf], bl0);
                    mma_bf16(d[mf][pr * 2 + 0], al[mf], bh0);
                    mma_bf16(d[mf][pr * 2 + 1], ah[mf], bh1);
                    mma_bf16(d[mf][pr * 2 + 1], ah[mf], bl1);
                    mma_bf16(d[mf][pr * 2 + 1], al[mf], bh1);
                }
            }
        }
        __syncthreads();
    }

    if (EPIROPE) {
        // 128-col tiles never straddle a q/k/v boundary (1024 % 128 == 0)
        const int sec = n0 >> 10;            // 0=q 1=k 2=v
#pragma unroll
        for (int mf = 0; mf < 2; mf++) {
            int row = m0 + m_base + mf * 16 + (lane >> 2);
#pragma unroll
            for (int rr = 0; rr < 2; rr++) {
                int r = row + rr * 8;
                int t = r & (TT - 1), b = r >> 11;
#pragma unroll
                for (int nf = 0; nf < 8; nf++) {
                    int ncol = n0 + n_base + nf * 8 + 2 * (lane & 3);  // even
                    int h    = (ncol & 1023) >> 6;
                    int dcol = ncol & 63;
                    size_t obase = ((size_t)(b * HH + h) * TT + t) * DD + dcol;
                    float v0 = d[mf][nf][rr * 2 + 0] + bias[ncol];
                    float v1 = d[mf][nf][rr * 2 + 1] + bias[ncol + 1];
                    uint32_t hi, lo;
                    if (sec == 2) {
                        split2(v0, v1, hi, lo);
                        *(uint32_t*)&g_vh[obase] = hi;
                        *(uint32_t*)&g_vl[obase] = lo;
                    } else {
                        int i = dcol >> 1;
                        float c = cosT[t * 32 + i], s = sinT[t * 32 + i];
                        float r0 = v0 * c - v1 * s;
                        float r1 = v0 * s + v1 * c;
                        if (sec == 0) {
                            split2(r0 * 0.125f, r1 * 0.125f, hi, lo);
                            *(uint32_t*)&g_qh[obase] = hi;
                            *(uint32_t*)&g_ql[obase] = lo;
                        } else {
                            split2(r0, r1, hi, lo);
                            *(uint32_t*)&g_kh[obase] = hi;
                            *(uint32_t*)&g_kl[obase] = lo;
                        }
                    }
                }
            }
        }
    } else {
#pragma unroll
        for (int mf = 0; mf < 2; mf++) {
#pragma unroll
            for (int nf = 0; nf < 8; nf++) {
                int row = m0 + m_base + mf * 16 + (lane >> 2);
                int col = n0 + n_base + nf * 8 + 2 * (lane & 3);
                float bx = bias[col], by = bias[col + 1];
                float2 v0 = {d[mf][nf][0] + bx, d[mf][nf][1] + by};
                float2 v1 = {d[mf][nf][2] + bx, d[mf][nf][3] + by};
                *(float2*)&Cm[(size_t)row * N + col]       = v0;
                *(float2*)&Cm[(size_t)(row + 8) * N + col] = v1;
            }
        }
    }
}

// ---------------- tensor-core causal flash attention --------------------------
// BQ=128, BKV=64, 8 warps x 16 q-rows. Q frags register-resident; K/V per chunk.
// 2 CTAs/SM. Causal warp-skip: in the final chunk of each q-tile, warps 0-3 are
// fully masked (P==0, softmax state provably unchanged) -> skip compute body.
#define FKP 72
#define F_QH 0
#define F_QL 18432
#define F_KH 0
#define F_KL 9216
#define F_VH 18432
#define F_VL 27648
#define FLASH_SMEM 36864

__global__ void __launch_bounds__(256, 2)
flash_mma_kernel(const __nv_bfloat16* __restrict__ Qh,
                 const __nv_bfloat16* __restrict__ Ql,
                 const __nv_bfloat16* __restrict__ Kh,
                 const __nv_bfloat16* __restrict__ Kl,
                 const __nv_bfloat16* __restrict__ Vh,
                 const __nv_bfloat16* __restrict__ Vl)
{
    extern __shared__ __align__(16) unsigned char smem[];
    const uint32_t sb = smem_u32(smem);
    const int tid  = threadIdx.x;
    const int lane = tid & 31;
    const int w    = tid >> 5;

    const int qt = gridDim.x - 1 - blockIdx.x;   // heavy tiles first
    const int q0 = qt * 128;
    const int bh = blockIdx.y;
    const size_t gbase = (size_t)bh * TT * DD;

    // ---- load Q tile (hi/lo) into smem ----
#pragma unroll
    for (int it = 0; it < 4; it++) {
        int u = tid + it * 256;                  // 0..1023
        int row = u >> 3, c8 = (u & 7) * 8;
        size_t g = gbase + (size_t)(q0 + row) * DD + c8;
        int s = row * FKP + c8;
        *(uint4*)(smem + F_QH + s * 2) = *(const uint4*)(Qh + g);
        *(uint4*)(smem + F_QL + s * 2) = *(const uint4*)(Ql + g);
    }
    __syncthreads();

    // ---- Q fragments into registers ----
    const int a_m   = w * 16 + (lane & 7) + ((lane >> 3) & 1) * 8;
    const int a_khi = (lane >> 4) * 8;
    uint32_t qh[4][4], ql[4][4];
#pragma unroll
    for (int ks = 0; ks < 4; ks++) {
        uint32_t off = (uint32_t)(a_m * FKP + ks * 16 + a_khi) * 2;
        ldsm_x4(qh[ks], sb + F_QH + off);
        ldsm_x4(ql[ks], sb + F_QL + off);
    }
    __syncthreads();   // done with Q smem; reuse for K/V

    const int b_g   = lane >> 3;
    const int b_n8  = (b_g >> 1) * 8 + (lane & 7);
    const int b_k8  = (b_g & 1) * 8;
    const int v_r8  = (b_g & 1) * 8 + (lane & 7);
    const int v_c8  = (b_g >> 1) * 8;

    float o[8][4];
#pragma unroll
    for (int nf = 0; nf < 8; nf++)
#pragma unroll
        for (int j = 0; j < 4; j++) o[nf][j] = 0.f;
    float m0 = -1e30f, m1 = -1e30f, l0 = 0.f, l1 = 0.f;

    const int r0g = q0 + w * 16 + (lane >> 2);
    const int nchunk = 2 * qt + 2;
    const bool wlo = (w < 4);                // warp covers rows < q0+64

    for (int ch = 0; ch < nchunk; ch++) {
        const int kv0 = ch * 64;
        __syncthreads();   // previous chunk's smem reads done
#pragma unroll
        for (int it = 0; it < 2; it++) {
            int u = tid + it * 256;              // 0..511
            int row = u >> 3, c8 = (u & 7) * 8;
            size_t g = gbase + (size_t)(kv0 + row) * DD + c8;
            int s = (row * FKP + c8) * 2;
            *(uint4*)(smem + F_KH + s) = *(const uint4*)(Kh + g);
            *(uint4*)(smem + F_KL + s) = *(const uint4*)(Kl + g);
            *(uint4*)(smem + F_VH + s) = *(const uint4*)(Vh + g);
            *(uint4*)(smem + F_VL + s) = *(const uint4*)(Vl + g);
        }
        __syncthreads();

        // Fully-masked warp-chunk: last chunk, lower warps. P==0 exactly;
        // softmax state and O provably unchanged -> skip whole body.
        // (uniform per warp; warp still participated in loads + barriers)
        if (ch == 2 * qt + 1 && wlo) continue;

        // ---- S = Q K^T (3-term split) ----
        float s4[8][4];
#pragma unroll
        for (int nf = 0; nf < 8; nf++)
#pragma unroll
            for (int j = 0; j < 4; j++) s4[nf][j] = 0.f;

#pragma unroll
        for (int ks = 0; ks < 4; ks++) {
#pragma unroll
            for (int pr = 0; pr < 4; pr++) {
                uint32_t off = (uint32_t)((pr * 16 + b_n8) * FKP + ks * 16 + b_k8) * 2;
                uint32_t kh4[4], kl4[4];
                ldsm_x4(kh4, sb + F_KH + off);
                ldsm_x4(kl4, sb + F_KL + off);
                uint32_t bh0[2] = {kh4[0], kh4[1]}, bh1[2] = {kh4[2], kh4[3]};
                uint32_t bl0[2] = {kl4[0], kl4[1]}, bl1[2] = {kl4[2], kl4[3]};
                mma_bf16(s4[2 * pr], qh[ks], bh0);
                mma_bf16(s4[2 * pr], qh[ks], bl0);
                mma_bf16(s4[2 * pr], ql[ks], bh0);
                mma_bf16(s4[2 * pr + 1], qh[ks], bh1);
                mma_bf16(s4[2 * pr + 1], qh[ks], bl1);
                mma_bf16(s4[2 * pr + 1], ql[ks], bh1);
            }
        }

        // ---- causal mask: only the warp x chunk pairs that straddle the
        // diagonal need it (lower warps in chunk 2qt, upper warps in 2qt+1) ----
        if ((ch == 2 * qt && wlo) || (ch == 2 * qt + 1 && !wlo)) {
#pragma unroll
            for (int nf = 0; nf < 8; nf++) {
                int cbase = kv0 + nf * 8 + (lane & 3) * 2;
#pragma unroll
                for (int j = 0; j < 4; j++) {
                    int col = cbase + (j & 1);
                    int row = r0g + ((j >> 1) << 3);
                    if (col > row) s4[nf][j] = -1e30f;
                }
            }
        }

        // ---- online softmax ----
        float mx0 = -1e30f, mx1 = -1e30f;
#pragma unroll
        for (int nf = 0; nf < 8; nf++) {
            mx0 = fmaxf(mx0, fmaxf(s4[nf][0], s4[nf][1]));
            mx1 = fmaxf(mx1, fmaxf(s4[nf][2], s4[nf][3]));
        }
        mx0 = fmaxf(mx0, __shfl_xor_sync(0xffffffffu, mx0, 1));
        mx0 = fmaxf(mx0, __shfl_xor_sync(0xffffffffu, mx0, 2));
        mx1 = fmaxf(mx1, __shfl_xor_sync(0xffffffffu, mx1, 1));
        mx1 = fmaxf(mx1, __shfl_xor_sync(0xffffffffu, mx1, 2));
        float mn0 = fmaxf(m0, mx0), mn1 = fmaxf(m1, mx1);
        float al0 = __expf(m0 - mn0), al1 = __expf(m1 - mn1);
        float sum0 = 0.f, sum1 = 0.f;
#pragma unroll
        for (int nf = 0; nf < 8; nf++) {
            s4[nf][0] = __expf(s4[nf][0] - mn0);
            s4[nf][1] = __expf(s4[nf][1] - mn0);
            s4[nf][2] = __expf(s4[nf][2] - mn1);
            s4[nf][3] = __expf(s4[nf][3] - mn1);
            sum0 += s4[nf][0] + s4[nf][1];
            sum1 += s4[nf][2] + s4[nf][3];
        }
        sum0 += __shfl_xor_sync(0xffffffffu, sum0, 1);
        sum0 += __shfl_xor_sync(0xffffffffu, sum0, 2);
        sum1 += __shfl_xor_sync(0xffffffffu, sum1, 1);
        sum1 += __shfl_xor_sync(0xffffffffu, sum1, 2);
        l0 = l0 * al0 + sum0;  m0 = mn0;
        l1 = l1 * al1 + sum1;  m1 = mn1;
#pragma unroll
        for (int nf = 0; nf < 8; nf++) {
            o[nf][0] *= al0; o[nf][1] *= al0;
            o[nf][2] *= al1; o[nf][3] *= al1;
        }

        // ---- O += P V (3-term split, P from registers) ----
#pragma unroll
        for (int ks = 0; ks < 4; ks++) {
            uint32_t pa_h[4], pa_l[4];
            split2(s4[2 * ks][0],     s4[2 * ks][1],     pa_h[0], pa_l[0]);
            split2(s4[2 * ks][2],     s4[2 * ks][3],     pa_h[1], pa_l[1]);
            split2(s4[2 * ks + 1][0], s4[2 * ks + 1][1], pa_h[2], pa_l[2]);
            split2(s4[2 * ks + 1][2], s4[2 * ks + 1][3], pa_h[3], pa_l[3]);
#pragma unroll
            for (int pr = 0; pr < 4; pr++) {
                uint32_t off = (uint32_t)((ks * 16 + v_r8) * FKP + pr * 16 + v_c8) * 2;
                uint32_t vh4[4], vl4[4];
                ldsm_x4_t(vh4, sb + F_VH + off);
                ldsm_x4_t(vl4, sb + F_VL + off);
                uint32_t bh0[2] = {vh4[0], vh4[1]}, bh1[2] = {vh4[2], vh4[3]};
                uint32_t bl0[2] = {vl4[0], vl4[1]}, bl1[2] = {vl4[2], vl4[3]};
                mma_bf16(o[2 * pr], pa_h, bh0);
                mma_bf16(o[2 * pr], pa_h, bl0);
                mma_bf16(o[2 * pr], pa_l, bh0);
                mma_bf16(o[2 * pr + 1], pa_h, bh1);
                mma_bf16(o[2 * pr + 1], pa_h, bl1);
                mma_bf16(o[2 * pr + 1], pa_l, bh1);
            }
        }
    }

    // ---- epilogue: O /= l, write bf16 hi/lo to [B,T,C] ----
    float inv0 = 1.f / l0, inv1 = 1.f / l1;
    int b = bh >> 4, h = bh & 15;
    size_t base0 = ((size_t)(b * TT + r0g)) * CC + h * DD;
    size_t base1 = ((size_t)(b * TT + r0g + 8)) * CC + h * DD;
#pragma unroll
    for (int nf = 0; nf < 8; nf++) {
        int c = nf * 8 + (lane & 3) * 2;
        uint32_t hi, lo;
        split2(o[nf][0] * inv0, o[nf][1] * inv0, hi, lo);
        *(uint32_t*)&g_yhi[base0 + c] = hi;
        *(uint32_t*)&g_ylo[base0 + c] = lo;
        split2(o[nf][2] * inv1, o[nf][3] * inv1, hi, lo);
        *(uint32_t*)&g_yhi[base1 + c] = hi;
        *(uint32_t*)&g_ylo[base1 + c] = lo;
    }
}

// ---------------- launcher ----------------------------------------------------
extern "C" void kernel_launch(void* const* d_in, const int* in_sizes, int n_in,
                              void* d_out, int out_size)
{
    const float* x     = (const float*)d_in[0];
    const float* Wqkv  = (const float*)d_in[1];
    const float* bqkv  = (const float*)d_in[2];
    const float* Wproj = (const float*)d_in[3];
    const float* bproj = (const float*)d_in[4];
    const float* cosT  = (const float*)d_in[5];
    const float* sinT  = (const float*)d_in[6];
    float* out = (float*)d_out;

    __nv_bfloat16 *xhi, *xlo, *wqhi, *wqlo, *wphi, *wplo, *yhi, *ylo;
    __nv_bfloat16 *qh, *ql, *kh, *kl, *vh, *vl;
    cudaGetSymbolAddress((void**)&xhi,  g_xhi);
    cudaGetSymbolAddress((void**)&xlo,  g_xlo);
    cudaGetSymbolAddress((void**)&wqhi, g_wqhi);
    cudaGetSymbolAddress((void**)&wqlo, g_wqlo);
    cudaGetSymbolAddress((void**)&wphi, g_wphi);
    cudaGetSymbolAddress((void**)&wplo, g_wplo);
    cudaGetSymbolAddress((void**)&yhi,  g_yhi);
    cudaGetSymbolAddress((void**)&ylo,  g_ylo);
    cudaGetSymbolAddress((void**)&qh,   g_qh);
    cudaGetSymbolAddress((void**)&ql,   g_ql);
    cudaGetSymbolAddress((void**)&kh,   g_kh);
    cudaGetSymbolAddress((void**)&kl,   g_kl);
    cudaGetSymbolAddress((void**)&vh,   g_vh);
    cudaGetSymbolAddress((void**)&vl,   g_vl);

    static bool attr_set = false;
    if (!attr_set) {
        cudaFuncSetAttribute(gemm_mma_kernel<1>,
                             cudaFuncAttributeMaxDynamicSharedMemorySize, GSMEM);
        cudaFuncSetAttribute(gemm_mma_kernel<0>,
                             cudaFuncAttributeMaxDynamicSharedMemorySize, GSMEM);
        cudaFuncSetAttribute(flash_mma_kernel,
                             cudaFuncAttributeMaxDynamicSharedMemorySize, FLASH_SMEM);
        attr_set = true;
    }

    // pre-pass: split x; transpose+split weights
    split_kernel<<<(MM * CC + 255) / 256, 256>>>(x, xhi, xlo, MM * CC);
    tsplit_kernel<<<dim3(C3 / 32, CC / 32), dim3(32, 8)>>>(Wqkv, wqhi, wqlo, CC, C3);
    tsplit_kernel<<<dim3(CC / 32, CC / 32), dim3(32, 8)>>>(Wproj, wphi, wplo, CC, CC);

    // 1) QKV projection, fused bias+RoPE+split epilogue -> g_qh..g_vl
    gemm_mma_kernel<1><<<dim3(C3 / GBN, MM / GBM), 256, GSMEM>>>(
        xhi, xlo, wqhi, wqlo, bqkv, cosT, sinT, nullptr, C3, CC);

    // 2) tensor-core causal flash attention (writes yhi/ylo in [B,T,C])
    flash_mma_kernel<<<dim3(TT / 128, BB * HH), 256, FLASH_SMEM>>>(
        qh, ql, kh, kl, vh, vl);

    // 3) output projection
    gemm_mma_kernel<0><<<dim3(CC / GBN, MM / GBM), 256, GSMEM>>>(
        yhi, ylo, wphi, wplo, bproj, nullptr, nullptr, out, CC, CC);
}

// round 15
// speedup vs baseline: 1.1096x; 1.0154x over previous
#include <cuda_runtime.h>
#include <cuda_bf16.h>
#include <cstdint>

#define BB   2
#define TT   2048
#define CC   1024
#define HH   16
#define DD   64
#define C3   3072
#define MM   (BB * TT)        // 4096

// ---------------- scratch (static device globals; no allocations) -------------
__device__ __nv_bfloat16 g_xhi[MM * CC];           // x split [M,K]
__device__ __nv_bfloat16 g_xlo[MM * CC];
__device__ __nv_bfloat16 g_wqhi[C3 * CC];          // Wqkv^T split [N,K]
__device__ __nv_bfloat16 g_wqlo[C3 * CC];
__device__ __nv_bfloat16 g_wphi[CC * CC];          // Wproj^T split [N,K]
__device__ __nv_bfloat16 g_wplo[CC * CC];
__device__ __nv_bfloat16 g_yhi[MM * CC];           // attention out split [B,T,C]
__device__ __nv_bfloat16 g_ylo[MM * CC];

// Q/K/V bf16 hi/lo in [B,H,T,D] (Q pre-scaled by 1/8)
__device__ __nv_bfloat16 g_qh[MM * CC];
__device__ __nv_bfloat16 g_ql[MM * CC];
__device__ __nv_bfloat16 g_kh[MM * CC];
__device__ __nv_bfloat16 g_kl[MM * CC];
__device__ __nv_bfloat16 g_vh[MM * CC];
__device__ __nv_bfloat16 g_vl[MM * CC];

// ---------------- helpers ------------------------------------------------------
__device__ __forceinline__ uint32_t smem_u32(const void* p) {
    uint32_t a;
    asm("{ .reg .u64 t; cvta.to.shared.u64 t, %1; cvt.u32.u64 %0, t; }"
        : "=r"(a) : "l"(p));
    return a;
}

__device__ __forceinline__ void ldsm_x4(uint32_t r[4], uint32_t addr) {
    asm volatile("ldmatrix.sync.aligned.m8n8.x4.shared.b16 {%0,%1,%2,%3}, [%4];"
                 : "=r"(r[0]), "=r"(r[1]), "=r"(r[2]), "=r"(r[3]) : "r"(addr));
}

__device__ __forceinline__ void ldsm_x4_t(uint32_t r[4], uint32_t addr) {
    asm volatile("ldmatrix.sync.aligned.m8n8.x4.trans.shared.b16 {%0,%1,%2,%3}, [%4];"
                 : "=r"(r[0]), "=r"(r[1]), "=r"(r[2]), "=r"(r[3]) : "r"(addr));
}

__device__ __forceinline__ void mma_bf16(float d[4], const uint32_t a[4],
                                         const uint32_t b[2]) {
    asm volatile(
        "mma.sync.aligned.m16n8k16.row.col.f32.bf16.bf16.f32 "
        "{%0,%1,%2,%3}, {%4,%5,%6,%7}, {%8,%9}, {%0,%1,%2,%3};"
        : "+f"(d[0]), "+f"(d[1]), "+f"(d[2]), "+f"(d[3])
        : "r"(a[0]), "r"(a[1]), "r"(a[2]), "r"(a[3]), "r"(b[0]), "r"(b[1]));
}

// split two floats into packed bf16x2 hi + lo(residual)
__device__ __forceinline__ void split2(float a, float b, uint32_t& hi, uint32_t& lo) {
    __nv_bfloat162 h = __floats2bfloat162_rn(a, b);
    hi = *(uint32_t*)&h;
    float ra = a - __bfloat162float(h.x);
    float rb = b - __bfloat162float(h.y);
    __nv_bfloat162 l2 = __floats2bfloat162_rn(ra, rb);
    lo = *(uint32_t*)&l2;
}

// ---------------- pre-pass: fp32 -> bf16 hi/lo split --------------------------
__global__ void split_kernel(const float* __restrict__ A,
                             __nv_bfloat16* __restrict__ hi,
                             __nv_bfloat16* __restrict__ lo, int n)
{
    int i = blockIdx.x * 256 + threadIdx.x;
    if (i < n) {
        float v = A[i];
        __nv_bfloat16 h = __float2bfloat16(v);
        hi[i] = h;
        lo[i] = __float2bfloat16(v - __bfloat162float(h));
    }
}

// transpose + split: W [K,N] fp32 -> hi/lo [N,K] bf16
__global__ void tsplit_kernel(const float* __restrict__ W,
                              __nv_bfloat16* __restrict__ hi,
                              __nv_bfloat16* __restrict__ lo, int K, int N)
{
    __shared__ float t[32][33];
    int k0 = blockIdx.y * 32, n0 = blockIdx.x * 32;
    int tx = threadIdx.x, ty = threadIdx.y;   // block (32,8)
#pragma unroll
    for (int i = 0; i < 32; i += 8)
        t[ty + i][tx] = W[(size_t)(k0 + ty + i) * N + n0 + tx];
    __syncthreads();
#pragma unroll
    for (int i = 0; i < 32; i += 8) {
        float v = t[tx][ty + i];
        size_t o = (size_t)(n0 + ty + i) * K + k0 + tx;
        __nv_bfloat16 h = __float2bfloat16(v);
        hi[o] = h;
        lo[o] = __float2bfloat16(v - __bfloat162float(h));
    }
}

// ---------------- mma.sync bf16 split GEMM ------------------------------------
// C[M,N] = A[M,K] @ Bt[N,K]^T + bias, fp32 accum.
// CTA tile 128x128, BK=64, 8 warps (4m x 2n), warp tile 32x64.
// Single smem buffer (R10 structure — both explicit pipelining variants
// regressed; the 2-CTA/SM interleave is the overlap mechanism).
#define GBM 128
#define GBN 128
#define GBK 64
#define KPAD 72
#define OFF_AH 0
#define OFF_AL (128 * KPAD * 2)          // 18432
#define OFF_BH (2 * 128 * KPAD * 2)     // 36864
#define OFF_BL (3 * 128 * KPAD * 2)     // 55296
#define GSMEM  (4 * 128 * KPAD * 2)     // 73728 B

template <int EPIROPE>
__global__ void __launch_bounds__(256, 2)
gemm_mma_kernel(const __nv_bfloat16* __restrict__ Ahi,
                const __nv_bfloat16* __restrict__ Alo,
                const __nv_bfloat16* __restrict__ Bhi,
                const __nv_bfloat16* __restrict__ Blo,
                const float* __restrict__ bias,
                const float* __restrict__ cosT,
                const float* __restrict__ sinT,
                float* __restrict__ Cm,
                int N, int K)
{
    extern __shared__ __align__(16) unsigned char smem[];
    __nv_bfloat16* sAh = (__nv_bfloat16*)(smem + OFF_AH);
    __nv_bfloat16* sAl = (__nv_bfloat16*)(smem + OFF_AL);
    __nv_bfloat16* sBh = (__nv_bfloat16*)(smem + OFF_BH);
    __nv_bfloat16* sBl = (__nv_bfloat16*)(smem + OFF_BL);
    const uint32_t sb = smem_u32(smem);

    const int tid  = threadIdx.x;
    const int lane = tid & 31;
    const int w    = tid >> 5;
    const int m_base = (w & 3) * 32;    // warp m offset
    const int n_base = (w >> 2) * 64;   // warp n offset

    const int m0 = blockIdx.y * GBM;
    const int n0 = blockIdx.x * GBN;

    float d[2][8][4];
#pragma unroll
    for (int i = 0; i < 2; i++)
#pragma unroll
        for (int j = 0; j < 8; j++)
#pragma unroll
            for (int r = 0; r < 4; r++) d[i][j][r] = 0.f;

    const int a_m   = m_base + (lane & 7) + ((lane >> 3) & 1) * 8;
    const int a_khi = (lane >> 4) * 8;
    const int b_g   = lane >> 3;
    const int b_n8  = (b_g >> 1) * 8 + (lane & 7);
    const int b_k8  = (b_g & 1) * 8;

    for (int k0 = 0; k0 < K; k0 += GBK) {
#pragma unroll
        for (int it = 0; it < 4; it++) {
            int u = tid + it * 256;          // 0..1023
            int row = u >> 3, c8 = (u & 7) * 8;
            int s = row * KPAD + c8;
            size_t ga = (size_t)(m0 + row) * K + k0 + c8;
            size_t gb = (size_t)(n0 + row) * K + k0 + c8;
            *(uint4*)(sAh + s) = *(const uint4*)(Ahi + ga);
            *(uint4*)(sAl + s) = *(const uint4*)(Alo + ga);
            *(uint4*)(sBh + s) = *(const uint4*)(Bhi + gb);
            *(uint4*)(sBl + s) = *(const uint4*)(Blo + gb);
        }
        __syncthreads();

#pragma unroll
        for (int ks = 0; ks < 4; ks++) {
            const int koff = ks * 16;
            uint32_t ah[2][4], al[2][4];
#pragma unroll
            for (int mf = 0; mf < 2; mf++) {
                uint32_t off = (uint32_t)((a_m + mf * 16) * KPAD + koff + a_khi) * 2;
                ldsm_x4(ah[mf], sb + OFF_AH + off);
                ldsm_x4(al[mf], sb + OFF_AL + off);
            }
#pragma unroll
            for (int pr = 0; pr < 4; pr++) {
                uint32_t off = (uint32_t)((n_base + pr * 16 + b_n8) * KPAD + koff + b_k8) * 2;
                uint32_t rh[4], rl[4];
                ldsm_x4(rh, sb + OFF_BH + off);
                ldsm_x4(rl, sb + OFF_BL + off);
                uint32_t bh0[2] = {rh[0], rh[1]}, bh1[2] = {rh[2], rh[3]};
                uint32_t bl0[2] = {rl[0], rl[1]}, bl1[2] = {rl[2], rl[3]};
#pragma unroll
                for (int mf = 0; mf < 2; mf++) {
                    mma_bf16(d[mf][pr * 2 + 0], ah[mf], bh0);
                    mma_bf16(d[mf][pr * 2 + 0], ah[mf], bl0);
                    mma_bf16(d[mf][pr * 2 + 0], al[mf], bh0);
                    mma_bf16(d[mf][pr * 2 + 1], ah[mf], bh1);
                    mma_bf16(d[mf][pr * 2 + 1], ah[mf], bl1);
                    mma_bf16(d[mf][pr * 2 + 1], al[mf], bh1);
                }
            }
        }
        __syncthreads();
    }

    if (EPIROPE) {
        const int sec = n0 >> 10;            // 0=q 1=k 2=v
#pragma unroll
        for (int mf = 0; mf < 2; mf++) {
            int row = m0 + m_base + mf * 16 + (lane >> 2);
#pragma unroll
            for (int rr = 0; rr < 2; rr++) {
                int r = row + rr * 8;
                int t = r & (TT - 1), b = r >> 11;
#pragma unroll
                for (int nf = 0; nf < 8; nf++) {
                    int ncol = n0 + n_base + nf * 8 + 2 * (lane & 3);  // even
                    int h    = (ncol & 1023) >> 6;
                    int dcol = ncol & 63;
                    size_t obase = ((size_t)(b * HH + h) * TT + t) * DD + dcol;
                    float v0 = d[mf][nf][rr * 2 + 0] + bias[ncol];
                    float v1 = d[mf][nf][rr * 2 + 1] + bias[ncol + 1];
                    uint32_t hi, lo;
                    if (sec == 2) {
                        split2(v0, v1, hi, lo);
                        *(uint32_t*)&g_vh[obase] = hi;
                        *(uint32_t*)&g_vl[obase] = lo;
                    } else {
                        int i = dcol >> 1;
                        float c = cosT[t * 32 + i], s = sinT[t * 32 + i];
                        float r0 = v0 * c - v1 * s;
                        float r1 = v0 * s + v1 * c;
                        if (sec == 0) {
                            split2(r0 * 0.125f, r1 * 0.125f, hi, lo);
                            *(uint32_t*)&g_qh[obase] = hi;
                            *(uint32_t*)&g_ql[obase] = lo;
                        } else {
                            split2(r0, r1, hi, lo);
                            *(uint32_t*)&g_kh[obase] = hi;
                            *(uint32_t*)&g_kl[obase] = lo;
                        }
                    }
                }
            }
        }
    } else {
#pragma unroll
        for (int mf = 0; mf < 2; mf++) {
#pragma unroll
            for (int nf = 0; nf < 8; nf++) {
                int row = m0 + m_base + mf * 16 + (lane >> 2);
                int col = n0 + n_base + nf * 8 + 2 * (lane & 3);
                float bx = bias[col], by = bias[col + 1];
                float2 v0 = {d[mf][nf][0] + bx, d[mf][nf][1] + by};
                float2 v1 = {d[mf][nf][2] + bx, d[mf][nf][3] + by};
                *(float2*)&Cm[(size_t)row * N + col]       = v0;
                *(float2*)&Cm[(size_t)(row + 8) * N + col] = v1;
            }
        }
    }
}

// ---------------- tensor-core causal flash attention --------------------------
// BQ=128, KV staged 128 rows per barrier pair, processed as two 64-row halves.
// 8 warps x 16 q-rows; Q frags register-resident; 2 CTAs/SM.
// Halved barrier/load-phase count vs 64-row chunks; compute body per half is
// unchanged. Causal: lower warps skip half-1 of the diagonal chunk.
#define FKP 72
#define F_KH 0
#define F_KL 18432
#define F_VH 36864
#define F_VL 55296
#define FLASH_SMEM 73728
#define F_QH 0
#define F_QL 18432

__global__ void __launch_bounds__(256, 2)
flash_mma_kernel(const __nv_bfloat16* __restrict__ Qh,
                 const __nv_bfloat16* __restrict__ Ql,
                 const __nv_bfloat16* __restrict__ Kh,
                 const __nv_bfloat16* __restrict__ Kl,
                 const __nv_bfloat16* __restrict__ Vh,
                 const __nv_bfloat16* __restrict__ Vl)
{
    extern __shared__ __align__(16) unsigned char smem[];
    const uint32_t sb = smem_u32(smem);
    const int tid  = threadIdx.x;
    const int lane = tid & 31;
    const int w    = tid >> 5;

    const int qt = gridDim.x - 1 - blockIdx.x;   // heavy tiles first
    const int q0 = qt * 128;
    const int bh = blockIdx.y;
    const size_t gbase = (size_t)bh * TT * DD;

    // ---- stage Q tile (hi/lo) ----
#pragma unroll
    for (int it = 0; it < 4; it++) {
        int u = tid + it * 256;                  // 0..1023
        int row = u >> 3, c8 = (u & 7) * 8;
        size_t g = gbase + (size_t)(q0 + row) * DD + c8;
        int s = row * FKP + c8;
        *(uint4*)(smem + F_QH + s * 2) = *(const uint4*)(Qh + g);
        *(uint4*)(smem + F_QL + s * 2) = *(const uint4*)(Ql + g);
    }
    __syncthreads();

    // ---- Q fragments into registers ----
    const int a_m   = w * 16 + (lane & 7) + ((lane >> 3) & 1) * 8;
    const int a_khi = (lane >> 4) * 8;
    uint32_t qh[4][4], ql[4][4];
#pragma unroll
    for (int ks = 0; ks < 4; ks++) {
        uint32_t off = (uint32_t)(a_m * FKP + ks * 16 + a_khi) * 2;
        ldsm_x4(qh[ks], sb + F_QH + off);
        ldsm_x4(ql[ks], sb + F_QL + off);
    }
    __syncthreads();   // Q smem free; becomes KV stage

    const int b_g   = lane >> 3;
    const int b_n8  = (b_g >> 1) * 8 + (lane & 7);
    const int b_k8  = (b_g & 1) * 8;
    const int v_r8  = (b_g & 1) * 8 + (lane & 7);
    const int v_c8  = (b_g >> 1) * 8;

    float o[8][4];
#pragma unroll
    for (int nf = 0; nf < 8; nf++)
#pragma unroll
        for (int j = 0; j < 4; j++) o[nf][j] = 0.f;
    float m0 = -1e30f, m1 = -1e30f, l0 = 0.f, l1 = 0.f;

    const int r0g = q0 + w * 16 + (lane >> 2);
    const int nchunk = qt + 1;                   // 128-row chunks
    const bool wlo = (w < 4);                    // warp covers rows < q0+64

    for (int ch = 0; ch < nchunk; ch++) {
        __syncthreads();   // previous chunk's smem reads done
#pragma unroll
        for (int it = 0; it < 4; it++) {
            int u = tid + it * 256;              // 0..1023 (128 rows)
            int row = u >> 3, c8 = (u & 7) * 8;
            size_t g = gbase + (size_t)(ch * 128 + row) * DD + c8;
            int s = (row * FKP + c8) * 2;
            *(uint4*)(smem + F_KH + s) = *(const uint4*)(Kh + g);
            *(uint4*)(smem + F_KL + s) = *(const uint4*)(Kl + g);
            *(uint4*)(smem + F_VH + s) = *(const uint4*)(Vh + g);
            *(uint4*)(smem + F_VL + s) = *(const uint4*)(Vl + g);
        }
        __syncthreads();

        const bool diag = (ch == qt);

#pragma unroll
        for (int half = 0; half < 2; half++) {
            // fully-masked warp-half: skip (P==0 exactly; state unchanged)
            if (diag && half == 1 && wlo) continue;

            const int kv0 = ch * 128 + half * 64;
            const int h64 = half * 64;

            // ---- S = Q K^T (3-term split) ----
            float s4[8][4];
#pragma unroll
            for (int nf = 0; nf < 8; nf++)
#pragma unroll
                for (int j = 0; j < 4; j++) s4[nf][j] = 0.f;

#pragma unroll
            for (int ks = 0; ks < 4; ks++) {
#pragma unroll
                for (int pr = 0; pr < 4; pr++) {
                    uint32_t off = (uint32_t)((h64 + pr * 16 + b_n8) * FKP + ks * 16 + b_k8) * 2;
                    uint32_t kh4[4], kl4[4];
                    ldsm_x4(kh4, sb + F_KH + off);
                    ldsm_x4(kl4, sb + F_KL + off);
                    uint32_t bh0[2] = {kh4[0], kh4[1]}, bh1[2] = {kh4[2], kh4[3]};
                    uint32_t bl0[2] = {kl4[0], kl4[1]}, bl1[2] = {kl4[2], kl4[3]};
                    mma_bf16(s4[2 * pr], qh[ks], bh0);
                    mma_bf16(s4[2 * pr], qh[ks], bl0);
                    mma_bf16(s4[2 * pr], ql[ks], bh0);
                    mma_bf16(s4[2 * pr + 1], qh[ks], bh1);
                    mma_bf16(s4[2 * pr + 1], qh[ks], bl1);
                    mma_bf16(s4[2 * pr + 1], ql[ks], bh1);
                }
            }

            // ---- causal mask: only straddle pairs ----
            if (diag && ((half == 0 && wlo) || (half == 1 && !wlo))) {
#pragma unroll
                for (int nf = 0; nf < 8; nf++) {
                    int cbase = kv0 + nf * 8 + (lane & 3) * 2;
#pragma unroll
                    for (int j = 0; j < 4; j++) {
                        int col = cbase + (j & 1);
                        int row = r0g + ((j >> 1) << 3);
                        if (col > row) s4[nf][j] = -1e30f;
                    }
                }
            }

            // ---- online softmax ----
            float mx0 = -1e30f, mx1 = -1e30f;
#pragma unroll
            for (int nf = 0; nf < 8; nf++) {
                mx0 = fmaxf(mx0, fmaxf(s4[nf][0], s4[nf][1]));
                mx1 = fmaxf(mx1, fmaxf(s4[nf][2], s4[nf][3]));
            }
            mx0 = fmaxf(mx0, __shfl_xor_sync(0xffffffffu, mx0, 1));
            mx0 = fmaxf(mx0, __shfl_xor_sync(0xffffffffu, mx0, 2));
            mx1 = fmaxf(mx1, __shfl_xor_sync(0xffffffffu, mx1, 1));
            mx1 = fmaxf(mx1, __shfl_xor_sync(0xffffffffu, mx1, 2));
            float mn0 = fmaxf(m0, mx0), mn1 = fmaxf(m1, mx1);
            float al0 = __expf(m0 - mn0), al1 = __expf(m1 - mn1);
            float sum0 = 0.f, sum1 = 0.f;
#pragma unroll
            for (int nf = 0; nf < 8; nf++) {
                s4[nf][0] = __expf(s4[nf][0] - mn0);
                s4[nf][1] = __expf(s4[nf][1] - mn0);
                s4[nf][2] = __expf(s4[nf][2] - mn1);
                s4[nf][3] = __expf(s4[nf][3] - mn1);
                sum0 += s4[nf][0] + s4[nf][1];
                sum1 += s4[nf][2] + s4[nf][3];
            }
            sum0 += __shfl_xor_sync(0xffffffffu, sum0, 1);
            sum0 += __shfl_xor_sync(0xffffffffu, sum0, 2);
            sum1 += __shfl_xor_sync(0xffffffffu, sum1, 1);
            sum1 += __shfl_xor_sync(0xffffffffu, sum1, 2);
            l0 = l0 * al0 + sum0;  m0 = mn0;
            l1 = l1 * al1 + sum1;  m1 = mn1;
#pragma unroll
            for (int nf = 0; nf < 8; nf++) {
                o[nf][0] *= al0; o[nf][1] *= al0;
                o[nf][2] *= al1; o[nf][3] *= al1;
            }

            // ---- O += P V (3-term split, P from registers) ----
#pragma unroll
            for (int ks = 0; ks < 4; ks++) {
                uint32_t pa_h[4], pa_l[4];
                split2(s4[2 * ks][0],     s4[2 * ks][1],     pa_h[0], pa_l[0]);
                split2(s4[2 * ks][2],     s4[2 * ks][3],     pa_h[1], pa_l[1]);
                split2(s4[2 * ks + 1][0], s4[2 * ks + 1][1], pa_h[2], pa_l[2]);
                split2(s4[2 * ks + 1][2], s4[2 * ks + 1][3], pa_h[3], pa_l[3]);
#pragma unroll
                for (int pr = 0; pr < 4; pr++) {
                    uint32_t off = (uint32_t)((h64 + ks * 16 + v_r8) * FKP + pr * 16 + v_c8) * 2;
                    uint32_t vh4[4], vl4[4];
                    ldsm_x4_t(vh4, sb + F_VH + off);
                    ldsm_x4_t(vl4, sb + F_VL + off);
                    uint32_t bh0[2] = {vh4[0], vh4[1]}, bh1[2] = {vh4[2], vh4[3]};
                    uint32_t bl0[2] = {vl4[0], vl4[1]}, bl1[2] = {vl4[2], vl4[3]};
                    mma_bf16(o[2 * pr], pa_h, bh0);
                    mma_bf16(o[2 * pr], pa_h, bl0);
                    mma_bf16(o[2 * pr], pa_l, bh0);
                    mma_bf16(o[2 * pr + 1], pa_h, bh1);
                    mma_bf16(o[2 * pr + 1], pa_h, bl1);
                    mma_bf16(o[2 * pr + 1], pa_l, bh1);
                }
            }
        }
    }

    // ---- epilogue: O /= l, write bf16 hi/lo to [B,T,C] ----
    float inv0 = 1.f / l0, inv1 = 1.f / l1;
    int b = bh >> 4, h = bh & 15;
    size_t base0 = ((size_t)(b * TT + r0g)) * CC + h * DD;
    size_t base1 = ((size_t)(b * TT + r0g + 8)) * CC + h * DD;
#pragma unroll
    for (int nf = 0; nf < 8; nf++) {
        int c = nf * 8 + (lane & 3) * 2;
        uint32_t hi, lo;
        split2(o[nf][0] * inv0, o[nf][1] * inv0, hi, lo);
        *(uint32_t*)&g_yhi[base0 + c] = hi;
        *(uint32_t*)&g_ylo[base0 + c] = lo;
        split2(o[nf][2] * inv1, o[nf][3] * inv1, hi, lo);
        *(uint32_t*)&g_yhi[base1 + c] = hi;
        *(uint32_t*)&g_ylo[base1 + c] = lo;
    }
}

// ---------------- launcher ----------------------------------------------------
extern "C" void kernel_launch(void* const* d_in, const int* in_sizes, int n_in,
                              void* d_out, int out_size)
{
    const float* x     = (const float*)d_in[0];
    const float* Wqkv  = (const float*)d_in[1];
    const float* bqkv  = (const float*)d_in[2];
    const float* Wproj = (const float*)d_in[3];
    const float* bproj = (const float*)d_in[4];
    const float* cosT  = (const float*)d_in[5];
    const float* sinT  = (const float*)d_in[6];
    float* out = (float*)d_out;

    __nv_bfloat16 *xhi, *xlo, *wqhi, *wqlo, *wphi, *wplo, *yhi, *ylo;
    __nv_bfloat16 *qh, *ql, *kh, *kl, *vh, *vl;
    cudaGetSymbolAddress((void**)&xhi,  g_xhi);
    cudaGetSymbolAddress((void**)&xlo,  g_xlo);
    cudaGetSymbolAddress((void**)&wqhi, g_wqhi);
    cudaGetSymbolAddress((void**)&wqlo, g_wqlo);
    cudaGetSymbolAddress((void**)&wphi, g_wphi);
    cudaGetSymbolAddress((void**)&wplo, g_wplo);
    cudaGetSymbolAddress((void**)&yhi,  g_yhi);
    cudaGetSymbolAddress((void**)&ylo,  g_ylo);
    cudaGetSymbolAddress((void**)&qh,   g_qh);
    cudaGetSymbolAddress((void**)&ql,   g_ql);
    cudaGetSymbolAddress((void**)&kh,   g_kh);
    cudaGetSymbolAddress((void**)&kl,   g_kl);
    cudaGetSymbolAddress((void**)&vh,   g_vh);
    cudaGetSymbolAddress((void**)&vl,   g_vl);

    static bool attr_set = false;
    if (!attr_set) {
        cudaFuncSetAttribute(gemm_mma_kernel<1>,
                             cudaFuncAttributeMaxDynamicSharedMemorySize, GSMEM);
        cudaFuncSetAttribute(gemm_mma_kernel<0>,
                             cudaFuncAttributeMaxDynamicSharedMemorySize, GSMEM);
        cudaFuncSetAttribute(flash_mma_kernel,
                             cudaFuncAttributeMaxDynamicSharedMemorySize, FLASH_SMEM);
        attr_set = true;
    }

    // pre-pass: split x; transpose+split weights
    split_kernel<<<(MM * CC + 255) / 256, 256>>>(x, xhi, xlo, MM * CC);
    tsplit_kernel<<<dim3(C3 / 32, CC / 32), dim3(32, 8)>>>(Wqkv, wqhi, wqlo, CC, C3);
    tsplit_kernel<<<dim3(CC / 32, CC / 32), dim3(32, 8)>>>(Wproj, wphi, wplo, CC, CC);

    // 1) QKV projection, fused bias+RoPE+split epilogue -> g_qh..g_vl
    gemm_mma_kernel<1><<<dim3(C3 / GBN, MM / GBM), 256, GSMEM>>>(
        xhi, xlo, wqhi, wqlo, bqkv, cosT, sinT, nullptr, C3, CC);

    // 2) tensor-core causal flash attention (writes yhi/ylo in [B,T,C])
    flash_mma_kernel<<<dim3(TT / 128, BB * HH), 256, FLASH_SMEM>>>(
        qh, ql, kh, kl, vh, vl);

    // 3) output projection
    gemm_mma_kernel<0><<<dim3(CC / GBN, MM / GBM), 256, GSMEM>>>(
        yhi, ylo, wphi, wplo, bproj, nullptr, nullptr, out, CC, CC);
}